// round 3
// baseline (speedup 1.0000x reference)
#include <cuda_runtime.h>
#include <cuda_fp16.h>
#include <cstdint>

#define M_DIM 8192
#define K_DIM 4096
#define N_DIM 11008
#define NG_DIM 32

#define TILE 128
#define NT (N_DIM / TILE) /* 86 */
#define MT (M_DIM / TILE) /* 64 */
#define NTHREADS 512

// tcgen05 only legal when an arch-specific (sm_103a/sm_100a) device pass exists.
#if defined(__CUDA_ARCH_FEAT_SM103_ALL) || defined(__CUDA_ARCH_FEAT_SM100_ALL)
#define USE_TC 1
#else
#define USE_TC 0
#endif

// ---------------- scratch (static device arrays: allocation-free) ----------------
__device__ __half g_xhi[(size_t)M_DIM * K_DIM];
__device__ __half g_xlo[(size_t)M_DIM * K_DIM];
__device__ float  g_S[NG_DIM * M_DIM];   // S[g*M + m] = sum of x over group g

// ---------------- common helpers ----------------
__device__ __forceinline__ uint32_t smem_u32(const void* p) {
    uint32_t a;
    asm("{ .reg .u64 t; cvta.to.shared.u64 t, %1; cvt.u32.u64 %0, t; }" : "=r"(a) : "l"(p));
    return a;
}

// one packed int32 word -> 8 exact fp16 nibble values, K-ascending, as 4 u32
__device__ __forceinline__ void dequant8(uint32_t w, uint32_t r[4]) {
    const uint32_t MASK = 0x000F000Fu, BIAS = 0x64006400u;
    uint32_t q0 = ((w      ) & MASK) | BIAS;
    uint32_t q1 = ((w >>  4) & MASK) | BIAS;
    uint32_t q2 = ((w >>  8) & MASK) | BIAS;
    uint32_t q3 = ((w >> 12) & MASK) | BIAS;
    __half2 off1024 = *reinterpret_cast<const __half2*>(&BIAS);  // (1024, 1024)
    __half2 h0 = __hsub2(*reinterpret_cast<__half2*>(&q0), off1024);
    __half2 h1 = __hsub2(*reinterpret_cast<__half2*>(&q1), off1024);
    __half2 h2 = __hsub2(*reinterpret_cast<__half2*>(&q2), off1024);
    __half2 h3 = __hsub2(*reinterpret_cast<__half2*>(&q3), off1024);
    uint32_t b0 = *reinterpret_cast<uint32_t*>(&h0);
    uint32_t b1 = *reinterpret_cast<uint32_t*>(&h1);
    uint32_t b2 = *reinterpret_cast<uint32_t*>(&h2);
    uint32_t b3 = *reinterpret_cast<uint32_t*>(&h3);
    r[0] = __byte_perm(b0, b1, 0x5410);  // v0 v1
    r[1] = __byte_perm(b2, b3, 0x5410);  // v2 v3
    r[2] = __byte_perm(b0, b1, 0x7632);  // v4 v5
    r[3] = __byte_perm(b2, b3, 0x7632);  // v6 v7
}

// ---------------- prep: split x into fp16 hi/lo planes + group sums ----------------
__global__ void prep_kernel(const float* __restrict__ x) {
    int gwarp = (blockIdx.x * blockDim.x + threadIdx.x) >> 5;
    int lane  = threadIdx.x & 31;
    if (gwarp >= M_DIM * NG_DIM) return;
    int m = gwarp / NG_DIM;
    int g = gwarp % NG_DIM;
    size_t base = (size_t)m * K_DIM + (size_t)g * 128;
    const float* xr = x + base;
    float sum = 0.f;
#pragma unroll
    for (int j = 0; j < 4; j++) {
        float v = xr[lane + 32 * j];
        __half hi = __float2half_rn(v);
        __half lo = __float2half_rn(v - __half2float(hi));
        g_xhi[base + lane + 32 * j] = hi;
        g_xlo[base + lane + 32 * j] = lo;
        sum += v;
    }
#pragma unroll
    for (int o = 16; o > 0; o >>= 1) sum += __shfl_xor_sync(0xFFFFFFFFu, sum, o);
    if (lane == 0) g_S[g * M_DIM + m] = sum;
}

// =================== tcgen05 path helpers (only on arch-specific pass) ===================
#if USE_TC
__device__ __forceinline__ uint32_t elect_one() {
    uint32_t pred;
    asm volatile("{ .reg .pred p; elect.sync _|p, 0xFFFFFFFF; selp.b32 %0, 1, 0, p; }" : "=r"(pred));
    return pred;
}
#define MBAR_INIT(addr, cnt) \
    asm volatile("mbarrier.init.shared.b64 [%0], %1;" :: "r"(addr), "r"(cnt) : "memory")
#define MBAR_INVAL(addr) \
    asm volatile("mbarrier.inval.shared.b64 [%0];" :: "r"(addr) : "memory")
#define MBAR_WAIT_PARITY(mbar_addr, parity) do {                                   \
    uint32_t _mbar = (uint32_t)(mbar_addr);                                        \
    uint32_t _par  = (uint32_t)(parity);                                           \
    uint32_t _done;                                                                \
    asm volatile(                                                                  \
        "{\n\t.reg .pred p;\n\t"                                                   \
        "mbarrier.try_wait.parity.acquire.cta.shared::cta.b64 p, [%1], %2;\n\t"    \
        "selp.b32 %0, 1, 0, p;\n\t}"                                               \
        : "=r"(_done) : "r"(_mbar), "r"(_par) : "memory");                         \
    if (!_done) {                                                                  \
        asm volatile(                                                              \
            "{\n\t.reg .pred P1;\n\t"                                              \
            "WAIT_LOOP_%=:\n\t"                                                    \
            "mbarrier.try_wait.parity.acquire.cta.shared::cta.b64 P1, [%0], %1, 0x989680;\n\t" \
            "@P1 bra.uni WAIT_DONE_%=;\n\t"                                        \
            "bra.uni WAIT_LOOP_%=;\n\t"                                            \
            "WAIT_DONE_%=:\n\t}"                                                   \
            :: "r"(_mbar), "r"(_par) : "memory");                                  \
    }                                                                              \
} while (0)

#define TC_ALLOC(smem_addr, n) \
    asm volatile("tcgen05.alloc.cta_group::1.sync.aligned.shared::cta.b32 [%0], %1;" \
                 :: "r"(smem_addr), "r"(n) : "memory")
#define TC_DEALLOC(tmem, n) \
    asm volatile("tcgen05.dealloc.cta_group::1.sync.aligned.b32 %0, %1;" :: "r"(tmem), "r"(n))
#define TC_RELINQ() \
    asm volatile("tcgen05.relinquish_alloc_permit.cta_group::1.sync.aligned;")
#define TC_COMMIT(mbar) \
    asm volatile("tcgen05.commit.cta_group::1.mbarrier::arrive::one.shared::cluster.b64 [%0];" \
                 :: "r"(mbar) : "memory")
#define TC_WAIT_LD()      asm volatile("tcgen05.wait::ld.sync.aligned;" ::: "memory")
#define TC_FENCE_BEFORE() asm volatile("tcgen05.fence::before_thread_sync;" ::: "memory")
#define TC_FENCE_AFTER()  asm volatile("tcgen05.fence::after_thread_sync;" ::: "memory")
#define FENCE_ASYNC_SHARED() asm volatile("fence.proxy.async.shared::cta;" ::: "memory")

#define TC_LD_32X32B_X32(r, tmem_addr)                                             \
    asm volatile(                                                                  \
        "tcgen05.ld.sync.aligned.32x32b.x32.b32 "                                  \
        "{%0, %1, %2, %3, %4, %5, %6, %7, "                                        \
        " %8, %9, %10, %11, %12, %13, %14, %15, "                                  \
        " %16, %17, %18, %19, %20, %21, %22, %23, "                                \
        " %24, %25, %26, %27, %28, %29, %30, %31}, [%32];"                         \
        : "=r"((r)[0]),  "=r"((r)[1]),  "=r"((r)[2]),  "=r"((r)[3]),               \
          "=r"((r)[4]),  "=r"((r)[5]),  "=r"((r)[6]),  "=r"((r)[7]),               \
          "=r"((r)[8]),  "=r"((r)[9]),  "=r"((r)[10]), "=r"((r)[11]),              \
          "=r"((r)[12]), "=r"((r)[13]), "=r"((r)[14]), "=r"((r)[15]),              \
          "=r"((r)[16]), "=r"((r)[17]), "=r"((r)[18]), "=r"((r)[19]),              \
          "=r"((r)[20]), "=r"((r)[21]), "=r"((r)[22]), "=r"((r)[23]),              \
          "=r"((r)[24]), "=r"((r)[25]), "=r"((r)[26]), "=r"((r)[27]),              \
          "=r"((r)[28]), "=r"((r)[29]), "=r"((r)[30]), "=r"((r)[31])               \
        : "r"(tmem_addr))

__device__ __forceinline__ void mma_f16_ss(uint32_t d_tmem, uint64_t a_desc, uint64_t b_desc,
                                           uint32_t idesc, bool acc) {
    uint32_t en = acc ? 1u : 0u;
    asm volatile(
        "{\n\t.reg .pred p;\n\t"
        "setp.ne.u32 p, %4, 0;\n\t"
        "tcgen05.mma.cta_group::1.kind::f16 [%0], %1, %2, %3, {%5, %5, %5, %5}, p;\n\t}"
        :: "r"(d_tmem), "l"(a_desc), "l"(b_desc), "r"(idesc), "r"(en), "r"(0u)
        : "memory");
}

static constexpr uint64_t DESC_BASE_SW128 =
    (uint64_t(2) << 61) | (uint64_t(1) << 46) | (uint64_t(64) << 32) | (uint64_t(1) << 16);
#define MAKE_DESC(addr) (DESC_BASE_SW128 | ((uint64_t)((addr) >> 4) & 0x3FFF))
#define SWZ128(off) ((off) ^ (((off) >> 3) & 0x70))
#define MMA_IDESC 0x8200010u

// tc SMEM layout
#define OFF_AHI 1024
#define OFF_ALO (OFF_AHI + 32768)
#define OFF_B   (OFF_ALO + 32768)
#define OFF_SZ  (OFF_B + 32768)

__device__ __forceinline__ uint32_t ab_off(int row, int chunk16) {
    int atom_col = chunk16 >> 3;
    int inner_c  = chunk16 & 7;
    int atom_row = row >> 3;
    int inner_r  = row & 7;
    uint32_t off = (uint32_t)(atom_row + atom_col * 16) * 1024u
                 + (uint32_t)inner_r * 128u + (uint32_t)inner_c * 16u;
    return SWZ128(off);
}
#endif  // USE_TC

// =================== fallback (mma.sync) helpers ===================
#define FB_STRIDE_B 272                  /* (128+8) halves * 2B, 16B aligned */
#define FB_A0 0
#define FB_A1 34816
#define FB_B  69632
#define FB_SZ 104448
#define SMEM_BYTES 105472

#define LDSM_X4(r0, r1, r2, r3, addr) \
    asm volatile("ldmatrix.sync.aligned.m8n8.x4.shared.b16 {%0,%1,%2,%3}, [%4];" \
                 : "=r"(r0), "=r"(r1), "=r"(r2), "=r"(r3) : "r"(addr))

#define MMA16816(d, a, b0v, b1v) \
    asm volatile("mma.sync.aligned.m16n8k16.row.col.f32.f16.f16.f32 " \
                 "{%0,%1,%2,%3}, {%4,%5,%6,%7}, {%8,%9}, {%0,%1,%2,%3};" \
                 : "+f"((d)[0]), "+f"((d)[1]), "+f"((d)[2]), "+f"((d)[3]) \
                 : "r"((a)[0]), "r"((a)[1]), "r"((a)[2]), "r"((a)[3]), \
                   "r"(b0v), "r"(b1v))

// ---------------- main GEMM ----------------
__global__ void __launch_bounds__(NTHREADS, 1)
gemm_kernel(const int* __restrict__ Wq, const float* __restrict__ scales,
            const float* __restrict__ zeros, float* __restrict__ out) {
    extern __shared__ char smem[];
    uint32_t sb = smem_u32(smem);
    int tid  = threadIdx.x;
    int wid  = tid >> 5;
    int lane = tid & 31;

    int n0 = blockIdx.x * TILE;
    int m0 = blockIdx.y * TILE;

#if USE_TC
    // =========================== tcgen05 path ===========================
    int wg = tid >> 7;        // 0..3 -> column group (32 cols each)
    int sp = wid & 3;         // subpartition -> row group (32 rows each)

    if (wid == 0) { TC_ALLOC(sb + 0, 128); TC_RELINQ(); }
    if (tid == 0) MBAR_INIT(sb + 8, 1);
    __syncthreads();

    uint32_t tmem;
    asm volatile("ld.shared.b32 %0, [%1];" : "=r"(tmem) : "r"(sb + 0));

    float O[32];
#pragma unroll
    for (int c = 0; c < 32; c++) O[c] = 0.f;

    uint64_t dAhi = MAKE_DESC(sb + OFF_AHI);
    uint64_t dAlo = MAKE_DESC(sb + OFF_ALO);
    uint64_t dB   = MAKE_DESC(sb + OFF_B);

    int m_row = m0 + sp * 32 + lane;

    for (int g = 0; g < NG_DIM; g++) {
        int k0 = g * 128;
#pragma unroll
        for (int i = 0; i < 4; i++) {
            int idx = tid + i * NTHREADS;
            int row = idx >> 4;
            int c16 = idx & 15;
            size_t gsrc = (size_t)(m0 + row) * K_DIM + k0 + c16 * 8;
            uint32_t so = ab_off(row, c16);
            *(uint4*)(smem + OFF_AHI + so) = *(const uint4*)(g_xhi + gsrc);
            *(uint4*)(smem + OFF_ALO + so) = *(const uint4*)(g_xlo + gsrc);
        }
#pragma unroll
        for (int i = 0; i < 4; i++) {
            int idx = tid + i * NTHREADS;
            int kp  = idx >> 7;
            int nl  = idx & 127;
            uint32_t w = (uint32_t)Wq[(size_t)(g * 16 + kp) * N_DIM + n0 + nl];
            uint32_t r[4];
            dequant8(w, r);
            uint32_t so = ab_off(nl, kp);
            *(uint4*)(smem + OFF_B + so) = make_uint4(r[0], r[1], r[2], r[3]);
        }
        if (tid < 128) {
            ((float*)(smem + OFF_SZ))[tid]       = scales[(size_t)g * N_DIM + n0 + tid];
            ((float*)(smem + OFF_SZ))[128 + tid] = zeros[(size_t)g * N_DIM + n0 + tid];
        }
        FENCE_ASYNC_SHARED();
        __syncthreads();

        if (wid == 0) {
            TC_FENCE_AFTER();
            if (elect_one()) {
#pragma unroll
                for (int k16 = 0; k16 < 8; k16++) {
                    uint32_t doff = (uint32_t)(k16 >> 2) * 1024u + (uint32_t)(k16 & 3) * 2u;
                    mma_f16_ss(tmem, dAhi + doff, dB + doff, MMA_IDESC, k16 > 0);
                }
#pragma unroll
                for (int k16 = 0; k16 < 8; k16++) {
                    uint32_t doff = (uint32_t)(k16 >> 2) * 1024u + (uint32_t)(k16 & 3) * 2u;
                    mma_f16_ss(tmem, dAlo + doff, dB + doff, MMA_IDESC, true);
                }
                TC_COMMIT(sb + 8);
            }
        }

        MBAR_WAIT_PARITY(sb + 8, g & 1);
        TC_FENCE_AFTER();

        uint32_t p[32];
        TC_LD_32X32B_X32(p, tmem + wg * 32);
        TC_WAIT_LD();
        float Sv = g_S[g * M_DIM + m_row];
        const float* ssm = (const float*)(smem + OFF_SZ) + wg * 32;
        const float* zsm = ssm + 128;
#pragma unroll
        for (int c = 0; c < 32; c++) {
            float pv = __uint_as_float(p[c]);
            O[c] = fmaf(ssm[c], fmaf(-zsm[c], Sv, pv), O[c]);
        }
        TC_FENCE_BEFORE();
        __syncthreads();
    }

    float* orow = out + (size_t)m_row * N_DIM + n0 + wg * 32;
#pragma unroll
    for (int c = 0; c < 32; c += 4)
        *(float4*)(orow + c) = make_float4(O[c], O[c + 1], O[c + 2], O[c + 3]);

    __syncthreads();
    if (tid == 0) MBAR_INVAL(sb + 8);
    __syncthreads();
    if (wid == 0) TC_DEALLOC(tmem, 128);

#else
    // =========================== mma.sync fallback ===========================
    // 16 warps in 4x4 grid; each warp computes a 32x32 tile via m16n8k16.
    int wm = wid >> 2;                // warp row  (0..3) -> 32 m each
    int wn = wid & 3;                 // warp col  (0..3) -> 32 n each

    float acc[2][4][4];               // [m-tile][n-tile][frag]
    float O[2][4][4];
#pragma unroll
    for (int tm = 0; tm < 2; tm++)
#pragma unroll
        for (int tn = 0; tn < 4; tn++)
#pragma unroll
            for (int c = 0; c < 4; c++) { acc[tm][tn][c] = 0.f; O[tm][tn][c] = 0.f; }

    // per-lane ldmatrix base addresses
    uint32_t aHiAddr[2], aLoAddr[2], bAddr[2];
#pragma unroll
    for (int tm = 0; tm < 2; tm++) {
        int row = wm * 32 + tm * 16 + (lane & 15);
        uint32_t off = (uint32_t)row * FB_STRIDE_B + (uint32_t)(lane >> 4) * 16;
        aHiAddr[tm] = sb + FB_A0 + off;
        aLoAddr[tm] = sb + FB_A1 + off;
    }
#pragma unroll
    for (int j = 0; j < 2; j++) {
        int row = wn * 32 + j * 16 + ((lane >> 4) << 3) + (lane & 7);
        bAddr[j] = sb + FB_B + (uint32_t)row * FB_STRIDE_B + (uint32_t)((lane >> 3) & 1) * 16;
    }

    int m_base = m0 + wm * 32 + (lane >> 2);

    for (int g = 0; g < NG_DIM; g++) {
        int k0 = g * 128;
        __syncthreads();   // previous epilogue done before overwriting smem

        // A planes: 128 rows x 128 halves each, padded rows
#pragma unroll
        for (int i = 0; i < 4; i++) {
            int idx = tid + i * NTHREADS;
            int row = idx >> 4;
            int c16 = idx & 15;
            size_t gsrc = (size_t)(m0 + row) * K_DIM + k0 + c16 * 8;
            uint32_t so = (uint32_t)row * FB_STRIDE_B + (uint32_t)c16 * 16;
            *(uint4*)(smem + FB_A0 + so) = *(const uint4*)(g_xhi + gsrc);
            *(uint4*)(smem + FB_A1 + so) = *(const uint4*)(g_xlo + gsrc);
        }
        // B: dequant into [n][k] rows
#pragma unroll
        for (int i = 0; i < 4; i++) {
            int idx = tid + i * NTHREADS;
            int kp  = idx >> 7;
            int nl  = idx & 127;
            uint32_t w = (uint32_t)Wq[(size_t)(g * 16 + kp) * N_DIM + n0 + nl];
            uint32_t r[4];
            dequant8(w, r);
            uint32_t so = (uint32_t)nl * FB_STRIDE_B + (uint32_t)kp * 16;
            *(uint4*)(smem + FB_B + so) = make_uint4(r[0], r[1], r[2], r[3]);
        }
        if (tid < 128) {
            ((float*)(smem + FB_SZ))[tid]       = scales[(size_t)g * N_DIM + n0 + tid];
            ((float*)(smem + FB_SZ))[128 + tid] = zeros[(size_t)g * N_DIM + n0 + tid];
        }
        __syncthreads();

        // compute: 8 k16 steps, both planes into same accumulators
#pragma unroll
        for (int k16 = 0; k16 < 8; k16++) {
            uint32_t koff = (uint32_t)k16 * 32;
            uint32_t b[8];
            LDSM_X4(b[0], b[1], b[2], b[3], bAddr[0] + koff);
            LDSM_X4(b[4], b[5], b[6], b[7], bAddr[1] + koff);
#pragma unroll
            for (int tm = 0; tm < 2; tm++) {
                uint32_t a[4];
                LDSM_X4(a[0], a[1], a[2], a[3], aHiAddr[tm] + koff);
                MMA16816(acc[tm][0], a, b[0], b[1]);
                MMA16816(acc[tm][1], a, b[2], b[3]);
                MMA16816(acc[tm][2], a, b[4], b[5]);
                MMA16816(acc[tm][3], a, b[6], b[7]);
                LDSM_X4(a[0], a[1], a[2], a[3], aLoAddr[tm] + koff);
                MMA16816(acc[tm][0], a, b[0], b[1]);
                MMA16816(acc[tm][1], a, b[2], b[3]);
                MMA16816(acc[tm][2], a, b[4], b[5]);
                MMA16816(acc[tm][3], a, b[6], b[7]);
            }
        }

        // group epilogue: O += s*(P - z*S), reset P
        float sv[4];
        {
            const float* Sg = g_S + (size_t)g * M_DIM + m_base;
            sv[0] = Sg[0]; sv[1] = Sg[8]; sv[2] = Sg[16]; sv[3] = Sg[24];
        }
        const float* ssm = (const float*)(smem + FB_SZ);
        const float* zsm = ssm + 128;
#pragma unroll
        for (int tn = 0; tn < 4; tn++) {
            int nl = wn * 32 + tn * 8 + (lane & 3) * 2;
            float s0 = ssm[nl], s1 = ssm[nl + 1];
            float z0 = zsm[nl], z1 = zsm[nl + 1];
#pragma unroll
            for (int tm = 0; tm < 2; tm++) {
#pragma unroll
                for (int c = 0; c < 4; c++) {
                    float S = sv[tm * 2 + (c >> 1)];
                    float s = (c & 1) ? s1 : s0;
                    float z = (c & 1) ? z1 : z0;
                    O[tm][tn][c] = fmaf(s, fmaf(-z, S, acc[tm][tn][c]), O[tm][tn][c]);
                    acc[tm][tn][c] = 0.f;
                }
            }
        }
    }

    // store output
#pragma unroll
    for (int tm = 0; tm < 2; tm++) {
        int r1 = m0 + wm * 32 + tm * 16 + (lane >> 2);
#pragma unroll
        for (int tn = 0; tn < 4; tn++) {
            int nc = n0 + wn * 32 + tn * 8 + (lane & 3) * 2;
            *(float2*)(out + (size_t)r1 * N_DIM + nc)       = make_float2(O[tm][tn][0], O[tm][tn][1]);
            *(float2*)(out + (size_t)(r1 + 8) * N_DIM + nc) = make_float2(O[tm][tn][2], O[tm][tn][3]);
        }
    }
#endif
}

// ---------------- launch ----------------
extern "C" void kernel_launch(void* const* d_in, const int* in_sizes, int n_in,
                              void* d_out, int out_size) {
    const float* x      = (const float*)d_in[0];
    const int*   Wq     = (const int*)d_in[1];
    const float* scales = (const float*)d_in[2];
    const float* zeros  = (const float*)d_in[3];
    float* out = (float*)d_out;

    cudaFuncSetAttribute(gemm_kernel, cudaFuncAttributeMaxDynamicSharedMemorySize, SMEM_BYTES);

    int total_threads = M_DIM * NG_DIM * 32;
    prep_kernel<<<total_threads / 256, 256>>>(x);

    dim3 grid(NT, MT);
    gemm_kernel<<<grid, NTHREADS, SMEM_BYTES>>>(Wq, scales, zeros, out);
}